// round 1
// baseline (speedup 1.0000x reference)
#include <cuda_runtime.h>
#include <cuda_fp16.h>
#include <cuda_bf16.h>

#define N_NODES  100000
#define N_EDGES  1600000
#define D_H      128
#define N_GRAPHS 128

#define SCAN_BLK 1024
#define NBLK     ((N_NODES + SCAN_BLK - 1) / SCAN_BLK)   // 98

#define GR       64      // rows per GEMM block
#define POOLG    6       // smem pool graph capacity per block

// ---------------- device scratch (no allocations allowed) ----------------
__device__ int    g_deg[N_NODES];
__device__ float  g_dinv[N_NODES];
__device__ int    g_rowstart[N_NODES + 1];
__device__ int    g_cursor[N_NODES];
__device__ int    g_col[N_EDGES];
__device__ int    g_part[128];
__device__ __half g_xh[(size_t)N_NODES * D_H];
__device__ float  g_agg[(size_t)N_NODES * D_H];
__device__ float  g_pooled[N_GRAPHS * D_H];
__device__ int    g_cnt[N_GRAPHS];

// ---------------- helpers ----------------
__device__ __forceinline__ float4 ldh4(const __half* p) {
    uint2 u = *reinterpret_cast<const uint2*>(p);
    __half2 a = *reinterpret_cast<__half2*>(&u.x);
    __half2 b = *reinterpret_cast<__half2*>(&u.y);
    float2 fa = __half22float2(a), fb = __half22float2(b);
    return make_float4(fa.x, fa.y, fb.x, fb.y);
}

// ---------------- kernels ----------------
__global__ void k_zero() {
    int i = blockIdx.x * blockDim.x + threadIdx.x;
    if (i < N_NODES) g_deg[i] = 0;
    if (i < N_GRAPHS * D_H) g_pooled[i] = 0.f;
}

__global__ void k_xhalf(const float* __restrict__ x) {
    int i = blockIdx.x * blockDim.x + threadIdx.x;   // over N_NODES*32 float4s
    if (i >= N_NODES * (D_H / 4)) return;
    float4 f = reinterpret_cast<const float4*>(x)[i];
    __half2 h0 = __floats2half2_rn(f.x, f.y);
    __half2 h1 = __floats2half2_rn(f.z, f.w);
    uint2 u;
    u.x = *reinterpret_cast<unsigned*>(&h0);
    u.y = *reinterpret_cast<unsigned*>(&h1);
    reinterpret_cast<uint2*>(g_xh)[i] = u;
}

__global__ void k_deg(const int* __restrict__ ei) {
    int e = blockIdx.x * blockDim.x + threadIdx.x;
    if (e >= N_EDGES) return;
    atomicAdd(&g_deg[ei[N_EDGES + e]], 1);
}

__global__ void k_cnt(const int* __restrict__ batch) {
    __shared__ int lb[N_GRAPHS + 1];
    int t = threadIdx.x;
    if (t <= N_GRAPHS) {
        int lo = 0, hi = N_NODES;
        while (lo < hi) { int mid = (lo + hi) >> 1; if (batch[mid] < t) lo = mid + 1; else hi = mid; }
        lb[t] = lo;
    }
    __syncthreads();
    if (t < N_GRAPHS) g_cnt[t] = lb[t + 1] - lb[t];
}

__global__ void k_scan1() {
    int t = threadIdx.x, b = blockIdx.x;
    int i = b * SCAN_BLK + t;
    int d = (i < N_NODES) ? g_deg[i] : 0;
    if (i < N_NODES) g_dinv[i] = rsqrtf((float)(d + 1));
    int v = d;
    #pragma unroll
    for (int o = 1; o < 32; o <<= 1) { int n = __shfl_up_sync(0xffffffffu, v, o); if ((t & 31) >= o) v += n; }
    __shared__ int ws[32];
    if ((t & 31) == 31) ws[t >> 5] = v;
    __syncthreads();
    if (t < 32) {
        int s = ws[t];
        #pragma unroll
        for (int o = 1; o < 32; o <<= 1) { int n = __shfl_up_sync(0xffffffffu, s, o); if (t >= o) s += n; }
        ws[t] = s;
    }
    __syncthreads();
    int warpoff = (t >= 32) ? ws[(t >> 5) - 1] : 0;
    int excl = v - d + warpoff;
    if (i < N_NODES) g_rowstart[i] = excl;
    if (t == SCAN_BLK - 1) g_part[b] = excl + d;
}

__global__ void k_scan2() {
    int t = threadIdx.x;   // 128 threads
    int v = (t < NBLK) ? g_part[t] : 0;
    int inc = v;
    #pragma unroll
    for (int o = 1; o < 32; o <<= 1) { int n = __shfl_up_sync(0xffffffffu, inc, o); if ((t & 31) >= o) inc += n; }
    __shared__ int ws[4];
    if ((t & 31) == 31) ws[t >> 5] = inc;
    __syncthreads();
    if (t == 0) { int s = 0; for (int j = 0; j < 4; j++) { int x = ws[j]; ws[j] = s; s += x; } }
    __syncthreads();
    int excl = inc - v + ws[t >> 5];
    if (t < NBLK) g_part[t] = excl;
}

__global__ void k_scan3() {
    int i = blockIdx.x * blockDim.x + threadIdx.x;
    if (i < N_NODES) {
        int rs = g_rowstart[i] + g_part[i / SCAN_BLK];
        g_rowstart[i] = rs;
        g_cursor[i] = rs;
    }
    if (i == 0) g_rowstart[N_NODES] = N_EDGES;
}

__global__ void k_fill(const int* __restrict__ ei) {
    int e = blockIdx.x * blockDim.x + threadIdx.x;
    if (e >= N_EDGES) return;
    int s = ei[e], d = ei[N_EDGES + e];
    int p = atomicAdd(&g_cursor[d], 1);
    g_col[p] = s;
}

// pull-mode aggregation: agg[d] = dinv[d] * ( dinv[d]*x[d] + sum_{s->d} dinv[s]*x[s] )
__global__ void k_agg() {
    int warp = (blockIdx.x * blockDim.x + threadIdx.x) >> 5;
    int l = threadIdx.x & 31;
    if (warp >= N_NODES) return;
    int d = warp;
    const __half* xp = g_xh;
    float wd = g_dinv[d];
    float4 acc = ldh4(xp + (size_t)d * D_H + l * 4);
    acc.x *= wd; acc.y *= wd; acc.z *= wd; acc.w *= wd;
    int r0 = g_rowstart[d], r1 = g_rowstart[d + 1];
    int e = r0;
    for (; e + 2 <= r1; e += 2) {
        int s0 = g_col[e], s1 = g_col[e + 1];
        float w0 = g_dinv[s0], w1 = g_dinv[s1];
        float4 f0 = ldh4(xp + (size_t)s0 * D_H + l * 4);
        float4 f1 = ldh4(xp + (size_t)s1 * D_H + l * 4);
        acc.x += w0 * f0.x + w1 * f1.x;
        acc.y += w0 * f0.y + w1 * f1.y;
        acc.z += w0 * f0.z + w1 * f1.z;
        acc.w += w0 * f0.w + w1 * f1.w;
    }
    if (e < r1) {
        int s0 = g_col[e];
        float w0 = g_dinv[s0];
        float4 f0 = ldh4(xp + (size_t)s0 * D_H + l * 4);
        acc.x += w0 * f0.x; acc.y += w0 * f0.y; acc.z += w0 * f0.z; acc.w += w0 * f0.w;
    }
    acc.x *= wd; acc.y *= wd; acc.z *= wd; acc.w *= wd;
    reinterpret_cast<float4*>(g_agg)[(size_t)d * (D_H / 4) + l] = acc;
}

#define FMA4(A, s, Wv) { (A).x += (s)*(Wv).x; (A).y += (s)*(Wv).y; (A).z += (s)*(Wv).z; (A).w += (s)*(Wv).w; }

// GEMM (agg @ W + b) fused with PReLU, L2-normalize, mean-pool accumulation
__global__ __launch_bounds__(256) void k_gemm_epi(const float* __restrict__ W,
                                                  const float* __restrict__ b,
                                                  const float* __restrict__ pa,
                                                  const int* __restrict__ batch) {
    extern __shared__ float sm[];
    float* sW = sm;                          // 128*128
    float* sA = sW + D_H * D_H;              // GR*128
    float* sB = sA + GR * D_H;               // 128
    float* sP = sB + D_H;                    // 128
    float* sPool = sP + D_H;                 // POOLG*128
    int*   sBatch = (int*)(sPool + POOLG * D_H);  // GR

    int t = threadIdx.x;
    int row0 = blockIdx.x * GR;

    for (int i = t; i < D_H * (D_H / 4); i += 256)
        reinterpret_cast<float4*>(sW)[i] = reinterpret_cast<const float4*>(W)[i];
    for (int i = t; i < D_H / 4; i += 256) {
        reinterpret_cast<float4*>(sB)[i] = reinterpret_cast<const float4*>(b)[i];
        reinterpret_cast<float4*>(sP)[i] = reinterpret_cast<const float4*>(pa)[i];
    }
    for (int i = t; i < GR * (D_H / 4); i += 256) {
        int r = i >> 5;
        int gr = row0 + r;
        reinterpret_cast<float4*>(sA)[i] = (gr < N_NODES)
            ? reinterpret_cast<const float4*>(g_agg)[(size_t)gr * (D_H / 4) + (i & 31)]
            : make_float4(0.f, 0.f, 0.f, 0.f);
    }
    for (int i = t; i < GR; i += 256) sBatch[i] = (row0 + i < N_NODES) ? batch[row0 + i] : -1;
    for (int i = t; i < POOLG * D_H; i += 256) sPool[i] = 0.f;
    __syncthreads();

    int w = t >> 5, l = t & 31;
    int rbase = w * 8;
    const float* aR = sA + rbase * D_H;

    float4 acc[8];
    #pragma unroll
    for (int r = 0; r < 8; r++) acc[r] = make_float4(0.f, 0.f, 0.f, 0.f);

    for (int k = 0; k < D_H; k += 4) {
        float4 w0 = *reinterpret_cast<const float4*>(sW + (k + 0) * D_H + 4 * l);
        float4 w1 = *reinterpret_cast<const float4*>(sW + (k + 1) * D_H + 4 * l);
        float4 w2 = *reinterpret_cast<const float4*>(sW + (k + 2) * D_H + 4 * l);
        float4 w3 = *reinterpret_cast<const float4*>(sW + (k + 3) * D_H + 4 * l);
        #pragma unroll
        for (int r = 0; r < 8; r++) {
            float4 av = *reinterpret_cast<const float4*>(aR + r * D_H + k);
            FMA4(acc[r], av.x, w0);
            FMA4(acc[r], av.y, w1);
            FMA4(acc[r], av.z, w2);
            FMA4(acc[r], av.w, w3);
        }
    }

    // epilogue: +b, PReLU, L2 normalize (per row, across warp lanes)
    float4 bb = reinterpret_cast<const float4*>(sB)[l];
    float4 pp = reinterpret_cast<const float4*>(sP)[l];
    #pragma unroll
    for (int r = 0; r < 8; r++) {
        float4 v = acc[r];
        v.x += bb.x; v.y += bb.y; v.z += bb.z; v.w += bb.w;
        v.x = v.x > 0.f ? v.x : pp.x * v.x;
        v.y = v.y > 0.f ? v.y : pp.y * v.y;
        v.z = v.z > 0.f ? v.z : pp.z * v.z;
        v.w = v.w > 0.f ? v.w : pp.w * v.w;
        float ss = v.x * v.x + v.y * v.y + v.z * v.z + v.w * v.w;
        #pragma unroll
        for (int o = 16; o > 0; o >>= 1) ss += __shfl_xor_sync(0xffffffffu, ss, o);
        float inv = rsqrtf(fmaxf(ss, 1e-24f));
        v.x *= inv; v.y *= inv; v.z *= inv; v.w *= inv;
        acc[r] = v;
    }

    int nvalid = N_NODES - row0; if (nvalid > GR) nvalid = GR;
    int gmin = sBatch[0];
    int gmax = sBatch[nvalid - 1];
    int span = gmax - gmin + 1;

    if (span <= POOLG) {
        int cur = -2;
        float4 pacc = make_float4(0.f, 0.f, 0.f, 0.f);
        #pragma unroll
        for (int r = 0; r < 8; r++) {
            if (rbase + r >= nvalid) break;
            int g = sBatch[rbase + r];
            if (g != cur) {
                if (cur >= 0) {
                    int base = (cur - gmin) * D_H + 4 * l;
                    atomicAdd(&sPool[base + 0], pacc.x);
                    atomicAdd(&sPool[base + 1], pacc.y);
                    atomicAdd(&sPool[base + 2], pacc.z);
                    atomicAdd(&sPool[base + 3], pacc.w);
                }
                cur = g; pacc = make_float4(0.f, 0.f, 0.f, 0.f);
            }
            pacc.x += acc[r].x; pacc.y += acc[r].y; pacc.z += acc[r].z; pacc.w += acc[r].w;
        }
        if (cur >= 0) {
            int base = (cur - gmin) * D_H + 4 * l;
            atomicAdd(&sPool[base + 0], pacc.x);
            atomicAdd(&sPool[base + 1], pacc.y);
            atomicAdd(&sPool[base + 2], pacc.z);
            atomicAdd(&sPool[base + 3], pacc.w);
        }
        __syncthreads();
        for (int i = t; i < span * D_H; i += 256) {
            float vv = sPool[i];
            if (vv != 0.f) atomicAdd(&g_pooled[gmin * D_H + i], vv);
        }
    } else {
        #pragma unroll
        for (int r = 0; r < 8; r++) {
            if (rbase + r >= nvalid) break;
            int g = sBatch[rbase + r];
            atomicAdd(&g_pooled[g * D_H + 4 * l + 0], acc[r].x);
            atomicAdd(&g_pooled[g * D_H + 4 * l + 1], acc[r].y);
            atomicAdd(&g_pooled[g * D_H + 4 * l + 2], acc[r].z);
            atomicAdd(&g_pooled[g * D_H + 4 * l + 3], acc[r].w);
        }
        __syncthreads();
    }
}

__global__ void k_final(float* __restrict__ out) {
    int i = blockIdx.x * blockDim.x + threadIdx.x;
    if (i >= N_GRAPHS * D_H) return;
    float c = (float)g_cnt[i >> 7];
    out[i] = g_pooled[i] / fmaxf(c, 1.f);
}

// ---------------- launcher ----------------
extern "C" void kernel_launch(void* const* d_in, const int* in_sizes, int n_in,
                              void* d_out, int out_size) {
    const float* x     = (const float*)d_in[0];
    const int*   ei    = (const int*)d_in[1];
    const int*   batch = (const int*)d_in[2];
    const float* W     = (const float*)d_in[3];
    const float* b     = (const float*)d_in[4];
    const float* pa    = (const float*)d_in[5];
    float* out = (float*)d_out;

    const int SMEM_GEMM = (D_H * D_H + GR * D_H + D_H + D_H + POOLG * D_H) * 4 + GR * 4;
    cudaFuncSetAttribute(k_gemm_epi, cudaFuncAttributeMaxDynamicSharedMemorySize, SMEM_GEMM);

    k_zero<<<(N_NODES + 255) / 256, 256>>>();
    k_xhalf<<<(N_NODES * (D_H / 4) + 255) / 256, 256>>>(x);
    k_deg<<<(N_EDGES + 255) / 256, 256>>>(ei);
    k_cnt<<<1, 256>>>(batch);
    k_scan1<<<NBLK, SCAN_BLK>>>();
    k_scan2<<<1, 128>>>();
    k_scan3<<<(N_NODES + 255) / 256, 256>>>();
    k_fill<<<(N_EDGES + 255) / 256, 256>>>(ei);
    k_agg<<<(N_NODES * 32 + 255) / 256, 256>>>();
    k_gemm_epi<<<(N_NODES + GR - 1) / GR, 256, SMEM_GEMM>>>(W, b, pa, batch);
    k_final<<<(N_GRAPHS * D_H + 255) / 256, 256>>>(out);
}

// round 4
// speedup vs baseline: 1.3058x; 1.3058x over previous
#include <cuda_runtime.h>
#include <cuda_fp16.h>
#include <cuda_bf16.h>
#include <cstdint>

#define N_NODES  100000
#define N_EDGES  1600000
#define D_H      128
#define N_GRAPHS 128

#define SCAN_BLK 1024
#define NBLK     ((N_NODES + SCAN_BLK - 1) / SCAN_BLK)   // 98

#define TILE_M   128
#define N_TILES  ((N_NODES + TILE_M - 1) / TILE_M)       // 782
#define N_PAD    (N_TILES * TILE_M)                       // 100096

#define LDAH     136   // padded row stride in halves (272B) for smem A/B tiles
#define LDD      130   // padded row stride in floats for smem D (EVEN -> float2 aligned)

// ---------------- device scratch (no allocations allowed) ----------------
__device__ int    g_deg[N_NODES];
__device__ float  g_dinv[N_NODES];
__device__ int    g_rowstart[N_NODES + 1];
__device__ int    g_cursor[N_NODES];
__device__ int    g_col[N_EDGES];
__device__ int    g_part[128];
__device__ __half g_xh[(size_t)N_NODES * D_H];
__device__ __half g_aggh[(size_t)N_PAD * D_H];      // fp16 aggregated features (padded)
__device__ __half g_wt[D_H * D_H];                  // W^T row-major: g_wt[n*128+k] = W[k][n]
__device__ float  g_pooled[N_GRAPHS * D_H];
__device__ int    g_cnt[N_GRAPHS];

// ---------------- helpers ----------------
__device__ __forceinline__ uint32_t smem_u32(const void* p) {
    uint32_t a;
    asm("{ .reg .u64 t; cvta.to.shared.u64 t, %1; cvt.u32.u64 %0, t; }" : "=r"(a) : "l"(p));
    return a;
}
__device__ __forceinline__ float4 ldh4(const __half* p) {
    uint2 u = *reinterpret_cast<const uint2*>(p);
    __half2 a = *reinterpret_cast<__half2*>(&u.x);
    __half2 b = *reinterpret_cast<__half2*>(&u.y);
    float2 fa = __half22float2(a), fb = __half22float2(b);
    return make_float4(fa.x, fa.y, fb.x, fb.y);
}

// ---------------- small kernels ----------------
__global__ void k_zero() {
    int i = blockIdx.x * blockDim.x + threadIdx.x;
    if (i < N_NODES) g_deg[i] = 0;
    if (i < N_GRAPHS * D_H) g_pooled[i] = 0.f;
    if (i < N_GRAPHS) g_cnt[i] = 0;
    if (i < (N_PAD - N_NODES) * D_H / 8)   // zero pad rows of g_aggh (uint4 chunks)
        reinterpret_cast<uint4*>(g_aggh + (size_t)N_NODES * D_H)[i] = make_uint4(0, 0, 0, 0);
}

__global__ void k_xhalf(const float* __restrict__ x) {
    int i = blockIdx.x * blockDim.x + threadIdx.x;
    if (i >= N_NODES * (D_H / 4)) return;
    float4 f = reinterpret_cast<const float4*>(x)[i];
    __half2 h0 = __floats2half2_rn(f.x, f.y);
    __half2 h1 = __floats2half2_rn(f.z, f.w);
    uint2 u;
    u.x = *reinterpret_cast<unsigned*>(&h0);
    u.y = *reinterpret_cast<unsigned*>(&h1);
    reinterpret_cast<uint2*>(g_xh)[i] = u;
}

__global__ void k_deg(const int* __restrict__ ei) {
    int e = blockIdx.x * blockDim.x + threadIdx.x;
    if (e >= N_EDGES) return;
    atomicAdd(&g_deg[ei[N_EDGES + e]], 1);
}

__global__ void k_cnt2(const int* __restrict__ batch) {
    int i = blockIdx.x * blockDim.x + threadIdx.x;
    if (i < N_NODES) atomicAdd(&g_cnt[batch[i]], 1);
}

__global__ void k_wprep(const float* __restrict__ W) {
    int idx = blockIdx.x * blockDim.x + threadIdx.x;   // 16384
    if (idx >= D_H * D_H) return;
    int k = idx >> 7, n = idx & 127;                   // coalesced read of W[k][n]
    g_wt[n * D_H + k] = __float2half_rn(W[idx]);
}

__global__ void k_scan1() {
    int t = threadIdx.x, b = blockIdx.x;
    int i = b * SCAN_BLK + t;
    int d = (i < N_NODES) ? g_deg[i] : 0;
    if (i < N_NODES) g_dinv[i] = rsqrtf((float)(d + 1));
    int v = d;
    #pragma unroll
    for (int o = 1; o < 32; o <<= 1) { int n = __shfl_up_sync(0xffffffffu, v, o); if ((t & 31) >= o) v += n; }
    __shared__ int ws[32];
    if ((t & 31) == 31) ws[t >> 5] = v;
    __syncthreads();
    if (t < 32) {
        int s = ws[t];
        #pragma unroll
        for (int o = 1; o < 32; o <<= 1) { int n = __shfl_up_sync(0xffffffffu, s, o); if (t >= o) s += n; }
        ws[t] = s;
    }
    __syncthreads();
    int warpoff = (t >= 32) ? ws[(t >> 5) - 1] : 0;
    int excl = v - d + warpoff;
    if (i < N_NODES) g_rowstart[i] = excl;
    if (t == SCAN_BLK - 1) g_part[b] = excl + d;
}

__global__ void k_scan2() {
    int t = threadIdx.x;
    int v = (t < NBLK) ? g_part[t] : 0;
    int inc = v;
    #pragma unroll
    for (int o = 1; o < 32; o <<= 1) { int n = __shfl_up_sync(0xffffffffu, inc, o); if ((t & 31) >= o) inc += n; }
    __shared__ int ws[4];
    if ((t & 31) == 31) ws[t >> 5] = inc;
    __syncthreads();
    if (t == 0) { int s = 0; for (int j = 0; j < 4; j++) { int x = ws[j]; ws[j] = s; s += x; } }
    __syncthreads();
    int excl = inc - v + ws[t >> 5];
    if (t < NBLK) g_part[t] = excl;
}

__global__ void k_scan3() {
    int i = blockIdx.x * blockDim.x + threadIdx.x;
    if (i < N_NODES) {
        int rs = g_rowstart[i] + g_part[i / SCAN_BLK];
        g_rowstart[i] = rs;
        g_cursor[i] = rs;
    }
    if (i == 0) g_rowstart[N_NODES] = N_EDGES;
}

__global__ void k_fill(const int* __restrict__ ei) {
    int e = blockIdx.x * blockDim.x + threadIdx.x;
    if (e >= N_EDGES) return;
    int s = ei[e], d = ei[N_EDGES + e];
    int p = atomicAdd(&g_cursor[d], 1);
    g_col[p] = s;
}

// pull-mode aggregation -> fp16 output
__global__ void k_agg() {
    int warp = (blockIdx.x * blockDim.x + threadIdx.x) >> 5;
    int l = threadIdx.x & 31;
    if (warp >= N_NODES) return;
    int d = warp;
    const __half* xp = g_xh;
    float wd = g_dinv[d];
    float4 acc = ldh4(xp + (size_t)d * D_H + l * 4);
    acc.x *= wd; acc.y *= wd; acc.z *= wd; acc.w *= wd;
    int r0 = g_rowstart[d], r1 = g_rowstart[d + 1];
    int e = r0;
    for (; e + 2 <= r1; e += 2) {
        int s0 = g_col[e], s1 = g_col[e + 1];
        float w0 = g_dinv[s0], w1 = g_dinv[s1];
        float4 f0 = ldh4(xp + (size_t)s0 * D_H + l * 4);
        float4 f1 = ldh4(xp + (size_t)s1 * D_H + l * 4);
        acc.x += w0 * f0.x + w1 * f1.x;
        acc.y += w0 * f0.y + w1 * f1.y;
        acc.z += w0 * f0.z + w1 * f1.z;
        acc.w += w0 * f0.w + w1 * f1.w;
    }
    if (e < r1) {
        int s0 = g_col[e];
        float w0 = g_dinv[s0];
        float4 f0 = ldh4(xp + (size_t)s0 * D_H + l * 4);
        acc.x += w0 * f0.x; acc.y += w0 * f0.y; acc.z += w0 * f0.z; acc.w += w0 * f0.w;
    }
    acc.x *= wd; acc.y *= wd; acc.z *= wd; acc.w *= wd;
    __half2 h0 = __floats2half2_rn(acc.x, acc.y);
    __half2 h1 = __floats2half2_rn(acc.z, acc.w);
    uint2 u;
    u.x = *reinterpret_cast<unsigned*>(&h0);
    u.y = *reinterpret_cast<unsigned*>(&h1);
    reinterpret_cast<uint2*>(g_aggh)[(size_t)d * (D_H / 4) + l] = u;
}

// ---------------- mma.sync GEMM + fused epilogue ----------------
// smem layout (bytes from dynamic base):
#define SM_BIAS   0                       // 128 f32
#define SM_PRELU  512                     // 128 f32
#define SM_BATCH  1024                    // 128 int
#define SM_A      2048                    // 128 x LDAH halves = 34816B (swizzle-free, padded)
#define SM_B      (SM_A + 128 * LDAH * 2) // 34816B
#define SM_D      SM_A                    // reuse: 128 x LDD f32 = 66560B
#define SM_TOTAL  (SM_B + 128 * LDAH * 2) // 71680

#define LDSM_X4(r0, r1, r2, r3, addr) \
    asm volatile("ldmatrix.sync.aligned.m8n8.x4.shared.b16 {%0,%1,%2,%3}, [%4];" \
                 : "=r"(r0), "=r"(r1), "=r"(r2), "=r"(r3) : "r"(addr))

#define MMA16816(c, a0, a1, a2, a3, b0, b1) \
    asm volatile("mma.sync.aligned.m16n8k16.row.col.f32.f16.f16.f32 " \
                 "{%0,%1,%2,%3}, {%4,%5,%6,%7}, {%8,%9}, {%0,%1,%2,%3};" \
                 : "+f"((c)[0]), "+f"((c)[1]), "+f"((c)[2]), "+f"((c)[3]) \
                 : "r"(a0), "r"(a1), "r"(a2), "r"(a3), "r"(b0), "r"(b1))

__global__ __launch_bounds__(256) void k_mma_epi(const float* __restrict__ bias,
                                                 const float* __restrict__ pa,
                                                 const int* __restrict__ batch) {
    extern __shared__ __align__(1024) char sm[];
    int t = threadIdx.x;
    int w = t >> 5, l = t & 31;
    int row0 = blockIdx.x * TILE_M;

    // stage A tile (rows row0..row0+127) and B = W^T into padded smem
    for (int i = t; i < 2048; i += 256) {
        int r = i >> 4, c8 = i & 15;   // r: row, c8: 16B chunk (8 halves)
        uint4 va = reinterpret_cast<const uint4*>(g_aggh)[(size_t)(row0 + r) * 16 + c8];
        *reinterpret_cast<uint4*>(sm + SM_A + (r * LDAH + c8 * 8) * 2) = va;
        uint4 vb = reinterpret_cast<const uint4*>(g_wt)[i];
        *reinterpret_cast<uint4*>(sm + SM_B + (r * LDAH + c8 * 8) * 2) = vb;
    }
    for (int i = t; i < D_H; i += 256) {
        reinterpret_cast<float*>(sm + SM_BIAS)[i] = bias[i];
        reinterpret_cast<float*>(sm + SM_PRELU)[i] = pa[i];
        int rg = row0 + i;
        reinterpret_cast<int*>(sm + SM_BATCH)[i] = batch[rg < N_NODES ? rg : N_NODES - 1];
    }
    __syncthreads();

    uint32_t sA = smem_u32(sm + SM_A);
    uint32_t sB = smem_u32(sm + SM_B);

    // preload all 8 A k-chunk fragments for this warp's 16-row band
    uint32_t a[8][4];
    {
        uint32_t base = sA + ((w * 16 + (l & 15)) * LDAH + (l >> 4) * 8) * 2;
        #pragma unroll
        for (int k = 0; k < 8; k++)
            LDSM_X4(a[k][0], a[k][1], a[k][2], a[k][3], base + k * 32);  // +16 halves per chunk
    }

    float acc[16][4];
    #pragma unroll
    for (int nb = 0; nb < 16; nb++)
        #pragma unroll
        for (int j = 0; j < 4; j++) acc[nb][j] = 0.f;

    // B x4 fragment base: rows n = (2*nbp + (l/16))*8 + l%8, k-half select by (l/8)&1
    uint32_t bbase = sB + ((((l >> 4) * 8) + (l & 7)) * LDAH + ((l >> 3) & 1) * 8) * 2;
    #pragma unroll
    for (int k = 0; k < 8; k++) {
        #pragma unroll
        for (int nbp = 0; nbp < 8; nbp++) {
            uint32_t b0, b1, b2, b3;
            LDSM_X4(b0, b1, b2, b3, bbase + (nbp * 16 * LDAH) * 2 + k * 32);
            MMA16816(acc[2 * nbp], a[k][0], a[k][1], a[k][2], a[k][3], b0, b1);
            MMA16816(acc[2 * nbp + 1], a[k][0], a[k][1], a[k][2], a[k][3], b2, b3);
        }
    }

    __syncthreads();   // done reading A/B; D region reuses A/B smem

    // epilogue in registers: +bias, PReLU, row sumsq (quad shfl), normalize, stage to smem D
    {
        const float* sBias = reinterpret_cast<const float*>(sm + SM_BIAS);
        const float* sPrelu = reinterpret_cast<const float*>(sm + SM_PRELU);
        float* sD = reinterpret_cast<float*>(sm + SM_D);
        int quad = l >> 2, qlane = l & 3;
        int r_lo = w * 16 + quad, r_hi = r_lo + 8;

        float ss_lo = 0.f, ss_hi = 0.f;
        #pragma unroll
        for (int nb = 0; nb < 16; nb++) {
            int c0 = nb * 8 + qlane * 2;
            float b0 = sBias[c0], b1 = sBias[c0 + 1];
            float p0 = sPrelu[c0], p1 = sPrelu[c0 + 1];
            float v0 = acc[nb][0] + b0; v0 = v0 > 0.f ? v0 : v0 * p0;
            float v1 = acc[nb][1] + b1; v1 = v1 > 0.f ? v1 : v1 * p1;
            float v2 = acc[nb][2] + b0; v2 = v2 > 0.f ? v2 : v2 * p0;
            float v3 = acc[nb][3] + b1; v3 = v3 > 0.f ? v3 : v3 * p1;
            acc[nb][0] = v0; acc[nb][1] = v1; acc[nb][2] = v2; acc[nb][3] = v3;
            ss_lo += v0 * v0 + v1 * v1;
            ss_hi += v2 * v2 + v3 * v3;
        }
        ss_lo += __shfl_xor_sync(0xffffffffu, ss_lo, 1);
        ss_lo += __shfl_xor_sync(0xffffffffu, ss_lo, 2);
        ss_hi += __shfl_xor_sync(0xffffffffu, ss_hi, 1);
        ss_hi += __shfl_xor_sync(0xffffffffu, ss_hi, 2);
        float inv_lo = rsqrtf(fmaxf(ss_lo, 1e-24f));
        float inv_hi = rsqrtf(fmaxf(ss_hi, 1e-24f));

        #pragma unroll
        for (int nb = 0; nb < 16; nb++) {
            int c0 = nb * 8 + qlane * 2;
            *reinterpret_cast<float2*>(sD + r_lo * LDD + c0) =
                make_float2(acc[nb][0] * inv_lo, acc[nb][1] * inv_lo);
            *reinterpret_cast<float2*>(sD + r_hi * LDD + c0) =
                make_float2(acc[nb][2] * inv_hi, acc[nb][3] * inv_hi);
        }
    }
    __syncthreads();

    // pooling: 2 threads per column (rows 0-63 / 64-127), run-based flush to global
    {
        int c = t & 127;
        int r0 = (t >> 7) * 64;
        int nvalid = N_NODES - row0; if (nvalid > TILE_M) nvalid = TILE_M;
        int rend = r0 + 64; if (rend > nvalid) rend = nvalid;
        const float* sD = reinterpret_cast<const float*>(sm + SM_D);
        const int* sBatch = reinterpret_cast<const int*>(sm + SM_BATCH);
        int cur = -1;
        float acc2 = 0.f;
        for (int r = r0; r < rend; r++) {
            int g = sBatch[r];
            if (g != cur) {
                if (cur >= 0) atomicAdd(&g_pooled[cur * D_H + c], acc2);
                cur = g; acc2 = 0.f;
            }
            acc2 += sD[r * LDD + c];
        }
        if (cur >= 0) atomicAdd(&g_pooled[cur * D_H + c], acc2);
    }
}

__global__ void k_final(float* __restrict__ out) {
    int i = blockIdx.x * blockDim.x + threadIdx.x;
    if (i >= N_GRAPHS * D_H) return;
    float c = (float)g_cnt[i >> 7];
    out[i] = g_pooled[i] / fmaxf(c, 1.f);
}

// ---------------- launcher ----------------
extern "C" void kernel_launch(void* const* d_in, const int* in_sizes, int n_in,
                              void* d_out, int out_size) {
    const float* x     = (const float*)d_in[0];
    const int*   ei    = (const int*)d_in[1];
    const int*   batch = (const int*)d_in[2];
    const float* W     = (const float*)d_in[3];
    const float* b     = (const float*)d_in[4];
    const float* pa    = (const float*)d_in[5];
    float* out = (float*)d_out;

    cudaFuncSetAttribute(k_mma_epi, cudaFuncAttributeMaxDynamicSharedMemorySize, SM_TOTAL);

    k_zero<<<(N_NODES + 255) / 256, 256>>>();
    k_xhalf<<<(N_NODES * (D_H / 4) + 255) / 256, 256>>>(x);
    k_deg<<<(N_EDGES + 255) / 256, 256>>>(ei);
    k_cnt2<<<(N_NODES + 255) / 256, 256>>>(batch);
    k_wprep<<<(D_H * D_H + 255) / 256, 256>>>(W);
    k_scan1<<<NBLK, SCAN_BLK>>>();
    k_scan2<<<1, 128>>>();
    k_scan3<<<(N_NODES + 255) / 256, 256>>>();
    k_fill<<<(N_EDGES + 255) / 256, 256>>>(ei);
    k_agg<<<(N_NODES * 32 + 255) / 256, 256>>>();
    k_mma_epi<<<N_TILES, 256, SM_TOTAL>>>(b, pa, batch);
    k_final<<<(N_GRAPHS * D_H + 255) / 256, 256>>>(out);
}

// round 5
// speedup vs baseline: 1.6233x; 1.2432x over previous
#include <cuda_runtime.h>
#include <cuda_fp16.h>
#include <cuda_bf16.h>
#include <cstdint>

#define N_NODES  100000
#define N_EDGES  1600000
#define D_H      128
#define N_GRAPHS 128

#define SCAN_BLK 1024
#define NBLK     ((N_NODES + SCAN_BLK - 1) / SCAN_BLK)   // 98

#define TILE_M   128
#define N_TILES  ((N_NODES + TILE_M - 1) / TILE_M)       // 782
#define N_PAD    (N_TILES * TILE_M)                       // 100096

#define LDAH     136   // padded row stride in halves (272B) for smem A/B tiles
#define LDD      130   // padded row stride in floats for smem D (EVEN -> float2 aligned)

// ---------------- device scratch (no allocations allowed) ----------------
__device__ int    g_deg[N_NODES];
__device__ float  g_dinv[N_NODES];
__device__ int    g_rowstart[N_NODES + 1];
__device__ int    g_cursor[N_NODES];
__device__ int    g_col[N_EDGES];
__device__ int    g_part[128];
__device__ __half g_xh[(size_t)N_NODES * D_H];
__device__ __half g_aggh[(size_t)N_PAD * D_H];      // fp16 aggregated features (padded)
__device__ __half g_wt[D_H * D_H];                  // W^T row-major: g_wt[n*128+k] = W[k][n]
__device__ float  g_pooled[N_GRAPHS * D_H];
__device__ int    g_bound[N_GRAPHS + 1];            // graph start offsets (batch sorted)

// ---------------- helpers ----------------
__device__ __forceinline__ uint32_t smem_u32(const void* p) {
    uint32_t a;
    asm("{ .reg .u64 t; cvta.to.shared.u64 t, %1; cvt.u32.u64 %0, t; }" : "=r"(a) : "l"(p));
    return a;
}
__device__ __forceinline__ float4 ldh4(const __half* p) {
    uint2 u = *reinterpret_cast<const uint2*>(p);
    __half2 a = *reinterpret_cast<__half2*>(&u.x);
    __half2 b = *reinterpret_cast<__half2*>(&u.y);
    float2 fa = __half22float2(a), fb = __half22float2(b);
    return make_float4(fa.x, fa.y, fb.x, fb.y);
}

// ---------------- small kernels ----------------
__global__ void k_zero() {
    int i = blockIdx.x * blockDim.x + threadIdx.x;
    if (i < N_NODES) g_deg[i] = 0;
    if (i < N_GRAPHS * D_H) g_pooled[i] = 0.f;
    if (i < (N_PAD - N_NODES) * D_H / 8)   // zero pad rows of g_aggh (uint4 chunks)
        reinterpret_cast<uint4*>(g_aggh + (size_t)N_NODES * D_H)[i] = make_uint4(0, 0, 0, 0);
}

__global__ void k_xhalf(const float* __restrict__ x) {
    int i = blockIdx.x * blockDim.x + threadIdx.x;
    if (i >= N_NODES * (D_H / 4)) return;
    float4 f = reinterpret_cast<const float4*>(x)[i];
    __half2 h0 = __floats2half2_rn(f.x, f.y);
    __half2 h1 = __floats2half2_rn(f.z, f.w);
    uint2 u;
    u.x = *reinterpret_cast<unsigned*>(&h0);
    u.y = *reinterpret_cast<unsigned*>(&h1);
    reinterpret_cast<uint2*>(g_xh)[i] = u;
}

__global__ void k_deg(const int* __restrict__ ei) {
    int e = blockIdx.x * blockDim.x + threadIdx.x;
    if (e >= N_EDGES) return;
    atomicAdd(&g_deg[ei[N_EDGES + e]], 1);
}

// boundary-based graph sizes: batch is sorted, no atomics needed
__global__ void k_bounds(const int* __restrict__ batch) {
    int i = blockIdx.x * blockDim.x + threadIdx.x;
    if (i >= N_NODES) return;
    int b0 = batch[i];
    int b1 = (i + 1 < N_NODES) ? batch[i + 1] : N_GRAPHS;
    if (i == 0)
        for (int g = 0; g <= b0; g++) g_bound[g] = 0;
    for (int g = b0 + 1; g <= b1; g++) g_bound[g] = i + 1;
}

__global__ void k_wprep(const float* __restrict__ W) {
    int idx = blockIdx.x * blockDim.x + threadIdx.x;   // 16384
    if (idx >= D_H * D_H) return;
    int k = idx >> 7, n = idx & 127;                   // coalesced read of W[k][n]
    g_wt[n * D_H + k] = __float2half_rn(W[idx]);
}

__global__ void k_scan1() {
    int t = threadIdx.x, b = blockIdx.x;
    int i = b * SCAN_BLK + t;
    int d = (i < N_NODES) ? g_deg[i] : 0;
    if (i < N_NODES) g_dinv[i] = rsqrtf((float)(d + 1));
    int v = d;
    #pragma unroll
    for (int o = 1; o < 32; o <<= 1) { int n = __shfl_up_sync(0xffffffffu, v, o); if ((t & 31) >= o) v += n; }
    __shared__ int ws[32];
    if ((t & 31) == 31) ws[t >> 5] = v;
    __syncthreads();
    if (t < 32) {
        int s = ws[t];
        #pragma unroll
        for (int o = 1; o < 32; o <<= 1) { int n = __shfl_up_sync(0xffffffffu, s, o); if (t >= o) s += n; }
        ws[t] = s;
    }
    __syncthreads();
    int warpoff = (t >= 32) ? ws[(t >> 5) - 1] : 0;
    int excl = v - d + warpoff;
    if (i < N_NODES) g_rowstart[i] = excl;
    if (t == SCAN_BLK - 1) g_part[b] = excl + d;
}

__global__ void k_scan2() {
    int t = threadIdx.x;
    int v = (t < NBLK) ? g_part[t] : 0;
    int inc = v;
    #pragma unroll
    for (int o = 1; o < 32; o <<= 1) { int n = __shfl_up_sync(0xffffffffu, inc, o); if ((t & 31) >= o) inc += n; }
    __shared__ int ws[4];
    if ((t & 31) == 31) ws[t >> 5] = inc;
    __syncthreads();
    if (t == 0) { int s = 0; for (int j = 0; j < 4; j++) { int x = ws[j]; ws[j] = s; s += x; } }
    __syncthreads();
    int excl = inc - v + ws[t >> 5];
    if (t < NBLK) g_part[t] = excl;
}

__global__ void k_scan3() {
    int i = blockIdx.x * blockDim.x + threadIdx.x;
    if (i < N_NODES) {
        int rs = g_rowstart[i] + g_part[i / SCAN_BLK];
        g_rowstart[i] = rs;
        g_cursor[i] = rs;
    }
    if (i == 0) g_rowstart[N_NODES] = N_EDGES;
}

__global__ void k_fill(const int* __restrict__ ei) {
    int e = blockIdx.x * blockDim.x + threadIdx.x;
    if (e >= N_EDGES) return;
    int s = ei[e], d = ei[N_EDGES + e];
    int p = atomicAdd(&g_cursor[d], 1);
    g_col[p] = s;
}

// pull-mode aggregation -> fp16 output
__global__ void k_agg() {
    int warp = (blockIdx.x * blockDim.x + threadIdx.x) >> 5;
    int l = threadIdx.x & 31;
    if (warp >= N_NODES) return;
    int d = warp;
    const __half* xp = g_xh;
    float wd = g_dinv[d];
    float4 acc = ldh4(xp + (size_t)d * D_H + l * 4);
    acc.x *= wd; acc.y *= wd; acc.z *= wd; acc.w *= wd;
    int r0 = g_rowstart[d], r1 = g_rowstart[d + 1];
    int e = r0;
    for (; e + 4 <= r1; e += 4) {
        int s0 = g_col[e], s1 = g_col[e + 1], s2 = g_col[e + 2], s3 = g_col[e + 3];
        float w0 = g_dinv[s0], w1 = g_dinv[s1], w2 = g_dinv[s2], w3 = g_dinv[s3];
        float4 f0 = ldh4(xp + (size_t)s0 * D_H + l * 4);
        float4 f1 = ldh4(xp + (size_t)s1 * D_H + l * 4);
        float4 f2 = ldh4(xp + (size_t)s2 * D_H + l * 4);
        float4 f3 = ldh4(xp + (size_t)s3 * D_H + l * 4);
        acc.x += w0 * f0.x + w1 * f1.x + w2 * f2.x + w3 * f3.x;
        acc.y += w0 * f0.y + w1 * f1.y + w2 * f2.y + w3 * f3.y;
        acc.z += w0 * f0.z + w1 * f1.z + w2 * f2.z + w3 * f3.z;
        acc.w += w0 * f0.w + w1 * f1.w + w2 * f2.w + w3 * f3.w;
    }
    for (; e < r1; e++) {
        int s0 = g_col[e];
        float w0 = g_dinv[s0];
        float4 f0 = ldh4(xp + (size_t)s0 * D_H + l * 4);
        acc.x += w0 * f0.x; acc.y += w0 * f0.y; acc.z += w0 * f0.z; acc.w += w0 * f0.w;
    }
    acc.x *= wd; acc.y *= wd; acc.z *= wd; acc.w *= wd;
    __half2 h0 = __floats2half2_rn(acc.x, acc.y);
    __half2 h1 = __floats2half2_rn(acc.z, acc.w);
    uint2 u;
    u.x = *reinterpret_cast<unsigned*>(&h0);
    u.y = *reinterpret_cast<unsigned*>(&h1);
    reinterpret_cast<uint2*>(g_aggh)[(size_t)d * (D_H / 4) + l] = u;
}

// ---------------- mma.sync GEMM + fused epilogue ----------------
// smem layout (bytes from dynamic base):
#define SM_BIAS   0                       // 128 f32
#define SM_PRELU  512                     // 128 f32
#define SM_BATCH  1024                    // 128 int
#define SM_A      2048                    // 128 x LDAH halves = 34816B (swizzle-free, padded)
#define SM_B      (SM_A + 128 * LDAH * 2) // 34816B
#define SM_D      SM_A                    // reuse: 128 x LDD f32 = 66560B
#define SM_TOTAL  (SM_B + 128 * LDAH * 2) // 71680

#define LDSM_X4(r0, r1, r2, r3, addr) \
    asm volatile("ldmatrix.sync.aligned.m8n8.x4.shared.b16 {%0,%1,%2,%3}, [%4];" \
                 : "=r"(r0), "=r"(r1), "=r"(r2), "=r"(r3) : "r"(addr))

#define MMA16816(c, a0, a1, a2, a3, b0, b1) \
    asm volatile("mma.sync.aligned.m16n8k16.row.col.f32.f16.f16.f32 " \
                 "{%0,%1,%2,%3}, {%4,%5,%6,%7}, {%8,%9}, {%0,%1,%2,%3};" \
                 : "+f"((c)[0]), "+f"((c)[1]), "+f"((c)[2]), "+f"((c)[3]) \
                 : "r"(a0), "r"(a1), "r"(a2), "r"(a3), "r"(b0), "r"(b1))

__global__ __launch_bounds__(256) void k_mma_epi(const float* __restrict__ bias,
                                                 const float* __restrict__ pa,
                                                 const int* __restrict__ batch) {
    extern __shared__ __align__(1024) char sm[];
    int t = threadIdx.x;
    int w = t >> 5, l = t & 31;
    int row0 = blockIdx.x * TILE_M;

    // stage A tile (rows row0..row0+127) and B = W^T into padded smem
    for (int i = t; i < 2048; i += 256) {
        int r = i >> 4, c8 = i & 15;   // r: row, c8: 16B chunk (8 halves)
        uint4 va = reinterpret_cast<const uint4*>(g_aggh)[(size_t)(row0 + r) * 16 + c8];
        *reinterpret_cast<uint4*>(sm + SM_A + (r * LDAH + c8 * 8) * 2) = va;
        uint4 vb = reinterpret_cast<const uint4*>(g_wt)[i];
        *reinterpret_cast<uint4*>(sm + SM_B + (r * LDAH + c8 * 8) * 2) = vb;
    }
    for (int i = t; i < D_H; i += 256) {
        reinterpret_cast<float*>(sm + SM_BIAS)[i] = bias[i];
        reinterpret_cast<float*>(sm + SM_PRELU)[i] = pa[i];
        int rg = row0 + i;
        reinterpret_cast<int*>(sm + SM_BATCH)[i] = batch[rg < N_NODES ? rg : N_NODES - 1];
    }
    __syncthreads();

    uint32_t sA = smem_u32(sm + SM_A);
    uint32_t sB = smem_u32(sm + SM_B);

    // preload all 8 A k-chunk fragments for this warp's 16-row band
    uint32_t a[8][4];
    {
        uint32_t base = sA + ((w * 16 + (l & 15)) * LDAH + (l >> 4) * 8) * 2;
        #pragma unroll
        for (int k = 0; k < 8; k++)
            LDSM_X4(a[k][0], a[k][1], a[k][2], a[k][3], base + k * 32);  // +16 halves per chunk
    }

    float acc[16][4];
    #pragma unroll
    for (int nb = 0; nb < 16; nb++)
        #pragma unroll
        for (int j = 0; j < 4; j++) acc[nb][j] = 0.f;

    // B x4 fragment base: rows n = (2*nbp + (l/16))*8 + l%8, k-half select by (l/8)&1
    uint32_t bbase = sB + ((((l >> 4) * 8) + (l & 7)) * LDAH + ((l >> 3) & 1) * 8) * 2;
    #pragma unroll
    for (int k = 0; k < 8; k++) {
        #pragma unroll
        for (int nbp = 0; nbp < 8; nbp++) {
            uint32_t b0, b1, b2, b3;
            LDSM_X4(b0, b1, b2, b3, bbase + (nbp * 16 * LDAH) * 2 + k * 32);
            MMA16816(acc[2 * nbp], a[k][0], a[k][1], a[k][2], a[k][3], b0, b1);
            MMA16816(acc[2 * nbp + 1], a[k][0], a[k][1], a[k][2], a[k][3], b2, b3);
        }
    }

    __syncthreads();   // done reading A/B; D region reuses A/B smem

    // epilogue in registers: +bias, PReLU, row sumsq (quad shfl), normalize, stage to smem D
    {
        const float* sBias = reinterpret_cast<const float*>(sm + SM_BIAS);
        const float* sPrelu = reinterpret_cast<const float*>(sm + SM_PRELU);
        float* sD = reinterpret_cast<float*>(sm + SM_D);
        int quad = l >> 2, qlane = l & 3;
        int r_lo = w * 16 + quad, r_hi = r_lo + 8;

        float ss_lo = 0.f, ss_hi = 0.f;
        #pragma unroll
        for (int nb = 0; nb < 16; nb++) {
            int c0 = nb * 8 + qlane * 2;
            float b0 = sBias[c0], b1 = sBias[c0 + 1];
            float p0 = sPrelu[c0], p1 = sPrelu[c0 + 1];
            float v0 = acc[nb][0] + b0; v0 = v0 > 0.f ? v0 : v0 * p0;
            float v1 = acc[nb][1] + b1; v1 = v1 > 0.f ? v1 : v1 * p1;
            float v2 = acc[nb][2] + b0; v2 = v2 > 0.f ? v2 : v2 * p0;
            float v3 = acc[nb][3] + b1; v3 = v3 > 0.f ? v3 : v3 * p1;
            acc[nb][0] = v0; acc[nb][1] = v1; acc[nb][2] = v2; acc[nb][3] = v3;
            ss_lo += v0 * v0 + v1 * v1;
            ss_hi += v2 * v2 + v3 * v3;
        }
        ss_lo += __shfl_xor_sync(0xffffffffu, ss_lo, 1);
        ss_lo += __shfl_xor_sync(0xffffffffu, ss_lo, 2);
        ss_hi += __shfl_xor_sync(0xffffffffu, ss_hi, 1);
        ss_hi += __shfl_xor_sync(0xffffffffu, ss_hi, 2);
        float inv_lo = rsqrtf(fmaxf(ss_lo, 1e-24f));
        float inv_hi = rsqrtf(fmaxf(ss_hi, 1e-24f));

        #pragma unroll
        for (int nb = 0; nb < 16; nb++) {
            int c0 = nb * 8 + qlane * 2;
            *reinterpret_cast<float2*>(sD + r_lo * LDD + c0) =
                make_float2(acc[nb][0] * inv_lo, acc[nb][1] * inv_lo);
            *reinterpret_cast<float2*>(sD + r_hi * LDD + c0) =
                make_float2(acc[nb][2] * inv_hi, acc[nb][3] * inv_hi);
        }
    }
    __syncthreads();

    // pooling: 2 threads per column (rows 0-63 / 64-127), run-based flush to global
    {
        int c = t & 127;
        int r0 = (t >> 7) * 64;
        int nvalid = N_NODES - row0; if (nvalid > TILE_M) nvalid = TILE_M;
        int rend = r0 + 64; if (rend > nvalid) rend = nvalid;
        const float* sD = reinterpret_cast<const float*>(sm + SM_D);
        const int* sBatch = reinterpret_cast<const int*>(sm + SM_BATCH);
        int cur = -1;
        float acc2 = 0.f;
        for (int r = r0; r < rend; r++) {
            int g = sBatch[r];
            if (g != cur) {
                if (cur >= 0) atomicAdd(&g_pooled[cur * D_H + c], acc2);
                cur = g; acc2 = 0.f;
            }
            acc2 += sD[r * LDD + c];
        }
        if (cur >= 0) atomicAdd(&g_pooled[cur * D_H + c], acc2);
    }
}

__global__ void k_final(float* __restrict__ out) {
    int i = blockIdx.x * blockDim.x + threadIdx.x;
    if (i >= N_GRAPHS * D_H) return;
    int g = i >> 7;
    float c = (float)(g_bound[g + 1] - g_bound[g]);
    out[i] = g_pooled[i] / fmaxf(c, 1.f);
}

// ---------------- launcher ----------------
extern "C" void kernel_launch(void* const* d_in, const int* in_sizes, int n_in,
                              void* d_out, int out_size) {
    const float* x     = (const float*)d_in[0];
    const int*   ei    = (const int*)d_in[1];
    const int*   batch = (const int*)d_in[2];
    const float* W     = (const float*)d_in[3];
    const float* b     = (const float*)d_in[4];
    const float* pa    = (const float*)d_in[5];
    float* out = (float*)d_out;

    cudaFuncSetAttribute(k_mma_epi, cudaFuncAttributeMaxDynamicSharedMemorySize, SM_TOTAL);

    k_zero<<<(N_NODES + 255) / 256, 256>>>();
    k_xhalf<<<(N_NODES * (D_H / 4) + 255) / 256, 256>>>(x);
    k_deg<<<(N_EDGES + 255) / 256, 256>>>(ei);
    k_bounds<<<(N_NODES + 255) / 256, 256>>>(batch);
    k_wprep<<<(D_H * D_H + 255) / 256, 256>>>(W);
    k_scan1<<<NBLK, SCAN_BLK>>>();
    k_scan2<<<1, 128>>>();
    k_scan3<<<(N_NODES + 255) / 256, 256>>>();
    k_fill<<<(N_EDGES + 255) / 256, 256>>>(ei);
    k_agg<<<(N_NODES * 32 + 255) / 256, 256>>>();
    k_mma_epi<<<N_TILES, 256, SM_TOTAL>>>(b, pa, batch);
    k_final<<<(N_GRAPHS * D_H + 255) / 256, 256>>>(out);
}

// round 6
// speedup vs baseline: 1.7590x; 1.0836x over previous
#include <cuda_runtime.h>
#include <cuda_fp16.h>
#include <cuda_bf16.h>
#include <cstdint>

#define N_NODES  100000
#define N_EDGES  1600000
#define D_H      128
#define N_GRAPHS 128

#define SCAN_BLK 1024
#define NBLK     ((N_NODES + SCAN_BLK - 1) / SCAN_BLK)   // 98

#define TILE_M   128
#define N_TILES  ((N_NODES + TILE_M - 1) / TILE_M)       // 782
#define N_PAD    (N_TILES * TILE_M)                       // 100096

#define LDAH     136   // padded row stride in halves (272B) for smem A/B tiles
#define LDD      130   // padded row stride in floats for smem D (EVEN -> float2 aligned)

// ---------------- device scratch (zero-initialized at module load) ----------------
// INVARIANT: every kernel_launch call leaves g_deg and g_pooled fully zeroed
// (done in k_final), and the pad rows of g_aggh are never written -> stay zero.
__device__ int    g_deg[N_NODES];
__device__ float  g_dinv[N_NODES];
__device__ int    g_rowstart[N_NODES + 1];
__device__ int    g_cursor[N_NODES];
__device__ int    g_col[N_EDGES];
__device__ int    g_part[128];
__device__ __half g_xh[(size_t)N_NODES * D_H];      // xs = dinv * x, fp16
__device__ __half g_aggh[(size_t)N_PAD * D_H];      // fp16 aggregated features (padded)
__device__ __half g_wt[D_H * D_H];                  // W^T row-major: g_wt[n*128+k] = W[k][n]
__device__ float  g_pooled[N_GRAPHS * D_H];
__device__ int    g_bound[N_GRAPHS + 1];            // graph start offsets (batch sorted)

// ---------------- helpers ----------------
__device__ __forceinline__ uint32_t smem_u32(const void* p) {
    uint32_t a;
    asm("{ .reg .u64 t; cvta.to.shared.u64 t, %1; cvt.u32.u64 %0, t; }" : "=r"(a) : "l"(p));
    return a;
}
__device__ __forceinline__ float4 ldh4(const __half* p) {
    uint2 u = *reinterpret_cast<const uint2*>(p);
    __half2 a = *reinterpret_cast<__half2*>(&u.x);
    __half2 b = *reinterpret_cast<__half2*>(&u.y);
    float2 fa = __half22float2(a), fb = __half22float2(b);
    return make_float4(fa.x, fa.y, fb.x, fb.y);
}

// ---------------- fused preprocessing: deg atomics + graph bounds + W prep ----------------
__global__ void k_pre(const int* __restrict__ ei, const int* __restrict__ batch,
                      const float* __restrict__ W) {
    int i = blockIdx.x * blockDim.x + threadIdx.x;
    if (i < N_EDGES) atomicAdd(&g_deg[ei[N_EDGES + i]], 1);
    if (i < N_NODES) {
        int b0 = batch[i];
        int b1 = (i + 1 < N_NODES) ? batch[i + 1] : N_GRAPHS;
        if (i == 0)
            for (int g = 0; g <= b0; g++) g_bound[g] = 0;
        for (int g = b0 + 1; g <= b1; g++) g_bound[g] = i + 1;
    }
    if (i < D_H * D_H) {
        int k = i >> 7, n = i & 127;                   // coalesced read of W[k][n]
        g_wt[n * D_H + k] = __float2half_rn(W[i]);
    }
}

__global__ void k_scan1() {
    int t = threadIdx.x, b = blockIdx.x;
    int i = b * SCAN_BLK + t;
    int d = (i < N_NODES) ? g_deg[i] : 0;
    if (i < N_NODES) g_dinv[i] = rsqrtf((float)(d + 1));
    int v = d;
    #pragma unroll
    for (int o = 1; o < 32; o <<= 1) { int n = __shfl_up_sync(0xffffffffu, v, o); if ((t & 31) >= o) v += n; }
    __shared__ int ws[32];
    if ((t & 31) == 31) ws[t >> 5] = v;
    __syncthreads();
    if (t < 32) {
        int s = ws[t];
        #pragma unroll
        for (int o = 1; o < 32; o <<= 1) { int n = __shfl_up_sync(0xffffffffu, s, o); if (t >= o) s += n; }
        ws[t] = s;
    }
    __syncthreads();
    int warpoff = (t >= 32) ? ws[(t >> 5) - 1] : 0;
    int excl = v - d + warpoff;
    if (i < N_NODES) g_rowstart[i] = excl;
    if (t == SCAN_BLK - 1) g_part[b] = excl + d;
}

__global__ void k_scan2() {
    int t = threadIdx.x;
    int v = (t < NBLK) ? g_part[t] : 0;
    int inc = v;
    #pragma unroll
    for (int o = 1; o < 32; o <<= 1) { int n = __shfl_up_sync(0xffffffffu, inc, o); if ((t & 31) >= o) inc += n; }
    __shared__ int ws[4];
    if ((t & 31) == 31) ws[t >> 5] = inc;
    __syncthreads();
    if (t == 0) { int s = 0; for (int j = 0; j < 4; j++) { int x = ws[j]; ws[j] = s; s += x; } }
    __syncthreads();
    int excl = inc - v + ws[t >> 5];
    if (t < NBLK) g_part[t] = excl;
}

__global__ void k_scan3() {
    int i = blockIdx.x * blockDim.x + threadIdx.x;
    if (i < N_NODES) {
        int rs = g_rowstart[i] + g_part[i / SCAN_BLK];
        g_rowstart[i] = rs;
        g_cursor[i] = rs;
    }
    if (i == 0) g_rowstart[N_NODES] = N_EDGES;
}

// xs = dinv * x -> fp16 (after scan so dinv is ready)
__global__ void k_xs(const float* __restrict__ x) {
    int i = blockIdx.x * blockDim.x + threadIdx.x;
    if (i >= N_NODES * (D_H / 4)) return;
    float s = g_dinv[i >> 5];
    float4 f = reinterpret_cast<const float4*>(x)[i];
    __half2 h0 = __floats2half2_rn(f.x * s, f.y * s);
    __half2 h1 = __floats2half2_rn(f.z * s, f.w * s);
    uint2 u;
    u.x = *reinterpret_cast<unsigned*>(&h0);
    u.y = *reinterpret_cast<unsigned*>(&h1);
    reinterpret_cast<uint2*>(g_xh)[i] = u;
}

__global__ void k_fill(const int* __restrict__ ei) {
    int e = blockIdx.x * blockDim.x + threadIdx.x;
    if (e >= N_EDGES) return;
    int s = ei[e], d = ei[N_EDGES + e];
    int p = atomicAdd(&g_cursor[d], 1);
    g_col[p] = s;
}

// pull-mode aggregation: agg[d] = dinv[d] * ( xs[d] + sum_{s->d} xs[s] )  -> fp16
__global__ void k_agg() {
    int warp = (blockIdx.x * blockDim.x + threadIdx.x) >> 5;
    int l = threadIdx.x & 31;
    if (warp >= N_NODES) return;
    int d = warp;
    const __half* xp = g_xh;
    float wd = g_dinv[d];
    float4 acc = ldh4(xp + (size_t)d * D_H + l * 4);   // self term (already dinv-scaled)
    int r0 = g_rowstart[d], r1 = g_rowstart[d + 1];
    int e = r0;
    for (; e + 4 <= r1; e += 4) {
        int s0 = g_col[e], s1 = g_col[e + 1], s2 = g_col[e + 2], s3 = g_col[e + 3];
        float4 f0 = ldh4(xp + (size_t)s0 * D_H + l * 4);
        float4 f1 = ldh4(xp + (size_t)s1 * D_H + l * 4);
        float4 f2 = ldh4(xp + (size_t)s2 * D_H + l * 4);
        float4 f3 = ldh4(xp + (size_t)s3 * D_H + l * 4);
        acc.x += (f0.x + f1.x) + (f2.x + f3.x);
        acc.y += (f0.y + f1.y) + (f2.y + f3.y);
        acc.z += (f0.z + f1.z) + (f2.z + f3.z);
        acc.w += (f0.w + f1.w) + (f2.w + f3.w);
    }
    for (; e < r1; e++) {
        int s0 = g_col[e];
        float4 f0 = ldh4(xp + (size_t)s0 * D_H + l * 4);
        acc.x += f0.x; acc.y += f0.y; acc.z += f0.z; acc.w += f0.w;
    }
    acc.x *= wd; acc.y *= wd; acc.z *= wd; acc.w *= wd;
    __half2 h0 = __floats2half2_rn(acc.x, acc.y);
    __half2 h1 = __floats2half2_rn(acc.z, acc.w);
    uint2 u;
    u.x = *reinterpret_cast<unsigned*>(&h0);
    u.y = *reinterpret_cast<unsigned*>(&h1);
    reinterpret_cast<uint2*>(g_aggh)[(size_t)d * (D_H / 4) + l] = u;
}

// ---------------- mma.sync GEMM + fused epilogue ----------------
// smem layout (bytes from dynamic base):
#define SM_BIAS   0                       // 128 f32
#define SM_PRELU  512                     // 128 f32
#define SM_BATCH  1024                    // 128 int
#define SM_A      2048                    // 128 x LDAH halves = 34816B (swizzle-free, padded)
#define SM_B      (SM_A + 128 * LDAH * 2) // 34816B
#define SM_D      SM_A                    // reuse: 128 x LDD f32 = 66560B
#define SM_TOTAL  (SM_B + 128 * LDAH * 2) // 71680

#define LDSM_X4(r0, r1, r2, r3, addr) \
    asm volatile("ldmatrix.sync.aligned.m8n8.x4.shared.b16 {%0,%1,%2,%3}, [%4];" \
                 : "=r"(r0), "=r"(r1), "=r"(r2), "=r"(r3) : "r"(addr))

#define MMA16816(c, a0, a1, a2, a3, b0, b1) \
    asm volatile("mma.sync.aligned.m16n8k16.row.col.f32.f16.f16.f32 " \
                 "{%0,%1,%2,%3}, {%4,%5,%6,%7}, {%8,%9}, {%0,%1,%2,%3};" \
                 : "+f"((c)[0]), "+f"((c)[1]), "+f"((c)[2]), "+f"((c)[3]) \
                 : "r"(a0), "r"(a1), "r"(a2), "r"(a3), "r"(b0), "r"(b1))

__global__ __launch_bounds__(256) void k_mma_epi(const float* __restrict__ bias,
                                                 const float* __restrict__ pa,
                                                 const int* __restrict__ batch) {
    extern __shared__ __align__(1024) char sm[];
    int t = threadIdx.x;
    int w = t >> 5, l = t & 31;
    int row0 = blockIdx.x * TILE_M;

    // stage A tile (rows row0..row0+127) and B = W^T into padded smem
    for (int i = t; i < 2048; i += 256) {
        int r = i >> 4, c8 = i & 15;   // r: row, c8: 16B chunk (8 halves)
        uint4 va = reinterpret_cast<const uint4*>(g_aggh)[(size_t)(row0 + r) * 16 + c8];
        *reinterpret_cast<uint4*>(sm + SM_A + (r * LDAH + c8 * 8) * 2) = va;
        uint4 vb = reinterpret_cast<const uint4*>(g_wt)[i];
        *reinterpret_cast<uint4*>(sm + SM_B + (r * LDAH + c8 * 8) * 2) = vb;
    }
    for (int i = t; i < D_H; i += 256) {
        reinterpret_cast<float*>(sm + SM_BIAS)[i] = bias[i];
        reinterpret_cast<float*>(sm + SM_PRELU)[i] = pa[i];
        int rg = row0 + i;
        reinterpret_cast<int*>(sm + SM_BATCH)[i] = batch[rg < N_NODES ? rg : N_NODES - 1];
    }
    __syncthreads();

    uint32_t sA = smem_u32(sm + SM_A);
    uint32_t sB = smem_u32(sm + SM_B);

    // preload all 8 A k-chunk fragments for this warp's 16-row band
    uint32_t a[8][4];
    {
        uint32_t base = sA + ((w * 16 + (l & 15)) * LDAH + (l >> 4) * 8) * 2;
        #pragma unroll
        for (int k = 0; k < 8; k++)
            LDSM_X4(a[k][0], a[k][1], a[k][2], a[k][3], base + k * 32);  // +16 halves per chunk
    }

    float acc[16][4];
    #pragma unroll
    for (int nb = 0; nb < 16; nb++)
        #pragma unroll
        for (int j = 0; j < 4; j++) acc[nb][j] = 0.f;

    // B x4 fragment base: rows n = (2*nbp + (l/16))*8 + l%8, k-half select by (l/8)&1
    uint32_t bbase = sB + ((((l >> 4) * 8) + (l & 7)) * LDAH + ((l >> 3) & 1) * 8) * 2;
    #pragma unroll
    for (int k = 0; k < 8; k++) {
        #pragma unroll
        for (int nbp = 0; nbp < 8; nbp++) {
            uint32_t b0, b1, b2, b3;
            LDSM_X4(b0, b1, b2, b3, bbase + (nbp * 16 * LDAH) * 2 + k * 32);
            MMA16816(acc[2 * nbp], a[k][0], a[k][1], a[k][2], a[k][3], b0, b1);
            MMA16816(acc[2 * nbp + 1], a[k][0], a[k][1], a[k][2], a[k][3], b2, b3);
        }
    }

    __syncthreads();   // done reading A/B; D region reuses A/B smem

    // epilogue in registers: +bias, PReLU, row sumsq (quad shfl), normalize, stage to smem D
    {
        const float* sBias = reinterpret_cast<const float*>(sm + SM_BIAS);
        const float* sPrelu = reinterpret_cast<const float*>(sm + SM_PRELU);
        float* sD = reinterpret_cast<float*>(sm + SM_D);
        int quad = l >> 2, qlane = l & 3;
        int r_lo = w * 16 + quad, r_hi = r_lo + 8;

        float ss_lo = 0.f, ss_hi = 0.f;
        #pragma unroll
        for (int nb = 0; nb < 16; nb++) {
            int c0 = nb * 8 + qlane * 2;
            float b0 = sBias[c0], b1 = sBias[c0 + 1];
            float p0 = sPrelu[c0], p1 = sPrelu[c0 + 1];
            float v0 = acc[nb][0] + b0; v0 = v0 > 0.f ? v0 : v0 * p0;
            float v1 = acc[nb][1] + b1; v1 = v1 > 0.f ? v1 : v1 * p1;
            float v2 = acc[nb][2] + b0; v2 = v2 > 0.f ? v2 : v2 * p0;
            float v3 = acc[nb][3] + b1; v3 = v3 > 0.f ? v3 : v3 * p1;
            acc[nb][0] = v0; acc[nb][1] = v1; acc[nb][2] = v2; acc[nb][3] = v3;
            ss_lo += v0 * v0 + v1 * v1;
            ss_hi += v2 * v2 + v3 * v3;
        }
        ss_lo += __shfl_xor_sync(0xffffffffu, ss_lo, 1);
        ss_lo += __shfl_xor_sync(0xffffffffu, ss_lo, 2);
        ss_hi += __shfl_xor_sync(0xffffffffu, ss_hi, 1);
        ss_hi += __shfl_xor_sync(0xffffffffu, ss_hi, 2);
        float inv_lo = rsqrtf(fmaxf(ss_lo, 1e-24f));
        float inv_hi = rsqrtf(fmaxf(ss_hi, 1e-24f));

        #pragma unroll
        for (int nb = 0; nb < 16; nb++) {
            int c0 = nb * 8 + qlane * 2;
            *reinterpret_cast<float2*>(sD + r_lo * LDD + c0) =
                make_float2(acc[nb][0] * inv_lo, acc[nb][1] * inv_lo);
            *reinterpret_cast<float2*>(sD + r_hi * LDD + c0) =
                make_float2(acc[nb][2] * inv_hi, acc[nb][3] * inv_hi);
        }
    }
    __syncthreads();

    // pooling: 2 threads per column (rows 0-63 / 64-127), run-based flush to global
    {
        int c = t & 127;
        int r0 = (t >> 7) * 64;
        int nvalid = N_NODES - row0; if (nvalid > TILE_M) nvalid = TILE_M;
        int rend = r0 + 64; if (rend > nvalid) rend = nvalid;
        const float* sD = reinterpret_cast<const float*>(sm + SM_D);
        const int* sBatch = reinterpret_cast<const int*>(sm + SM_BATCH);
        int cur = -1;
        float acc2 = 0.f;
        for (int r = r0; r < rend; r++) {
            int g = sBatch[r];
            if (g != cur) {
                if (cur >= 0) atomicAdd(&g_pooled[cur * D_H + c], acc2);
                cur = g; acc2 = 0.f;
            }
            acc2 += sD[r * LDD + c];
        }
        if (cur >= 0) atomicAdd(&g_pooled[cur * D_H + c], acc2);
    }
}

// final output + reset state (deg, pooled) for the next call
__global__ void k_final(float* __restrict__ out) {
    int i = blockIdx.x * blockDim.x + threadIdx.x;
    if (i < N_GRAPHS * D_H) {
        int g = i >> 7;
        float c = (float)(g_bound[g + 1] - g_bound[g]);
        out[i] = g_pooled[i] / fmaxf(c, 1.f);
        g_pooled[i] = 0.f;
    }
    if (i < N_NODES) g_deg[i] = 0;
}

// ---------------- launcher ----------------
extern "C" void kernel_launch(void* const* d_in, const int* in_sizes, int n_in,
                              void* d_out, int out_size) {
    const float* x     = (const float*)d_in[0];
    const int*   ei    = (const int*)d_in[1];
    const int*   batch = (const int*)d_in[2];
    const float* W     = (const float*)d_in[3];
    const float* b     = (const float*)d_in[4];
    const float* pa    = (const float*)d_in[5];
    float* out = (float*)d_out;

    cudaFuncSetAttribute(k_mma_epi, cudaFuncAttributeMaxDynamicSharedMemorySize, SM_TOTAL);

    k_pre<<<(N_EDGES + 255) / 256, 256>>>(ei, batch, W);
    k_scan1<<<NBLK, SCAN_BLK>>>();
    k_scan2<<<1, 128>>>();
    k_scan3<<<(N_NODES + 255) / 256, 256>>>();
    k_xs<<<(N_NODES * (D_H / 4) + 255) / 256, 256>>>(x);
    k_fill<<<(N_EDGES + 255) / 256, 256>>>(ei);
    k_agg<<<(N_NODES * 32 + 255) / 256, 256>>>();
    k_mma_epi<<<N_TILES, 256, SM_TOTAL>>>(b, pa, batch);
    k_final<<<(N_NODES + 255) / 256, 256>>>(out);
}